// round 14
// baseline (speedup 1.0000x reference)
#include <cuda_runtime.h>
#include <cuda_bf16.h>
#include <math.h>
#include <stdint.h>

#define BB 4
#define KK 2048
#define NN 4096
#define CIN 61
#define NBK (BB*KK)
#define NPTS (BB*NN)
#define KNBR 32
#define CNTF 262144.0

typedef unsigned long long ull;

// ---------------- scratch globals ----------------
__device__ float g_part[(size_t)128 * NBK];
__device__ float g_A[516];
__device__ int   g_selg[(size_t)NBK * KNBR];
__device__ float g_rel[(size_t)NBK * KNBR * 3];
__device__ float g_h1pre[(size_t)NPTS * 128];
__device__ float g_s1pre[(size_t)NPTS * 64];
__device__ float g_epre[(size_t)NPTS * 4];
__device__ float g_sc[64], g_tc[64];
__device__ float g_C1[64], g_Ce[4];
__device__ float g_Wr1s[192], g_A1s[12];
// fragment-packed bf16 weights (hi/lo)
__device__ __align__(16) __nv_bfloat16 g_W2h[16384], g_W2l[16384];
__device__ __align__(16) __nv_bfloat16 g_W3h[8192],  g_W3l[8192];
__device__ __align__(16) __nv_bfloat16 g_S2h[4096],  g_S2l[4096];
__device__ __align__(16) __nv_bfloat16 g_S3h[4096],  g_S3l[4096];

// ---------------- helpers ----------------
__device__ __forceinline__ void mma16816(float* d, const uint32_t* a, uint32_t b0, uint32_t b1) {
    asm volatile("mma.sync.aligned.m16n8k16.row.col.f32.bf16.bf16.f32 "
        "{%0,%1,%2,%3}, {%4,%5,%6,%7}, {%8,%9}, {%0,%1,%2,%3};"
        : "+f"(d[0]), "+f"(d[1]), "+f"(d[2]), "+f"(d[3])
        : "r"(a[0]), "r"(a[1]), "r"(a[2]), "r"(a[3]), "r"(b0), "r"(b1));
}
__device__ __forceinline__ void split_store(float v0, float v1, char* pH, char* pL) {
    uint32_t h;
    asm("cvt.rn.bf16x2.f32 %0, %1, %2;" : "=r"(h) : "f"(v1), "f"(v0));
    float r0 = v0 - __uint_as_float(h << 16);
    float r1 = v1 - __uint_as_float(h & 0xFFFF0000u);
    uint32_t lo;
    asm("cvt.rn.bf16x2.f32 %0, %1, %2;" : "=r"(lo) : "f"(r1), "f"(r0));
    *(uint32_t*)pH = h;
    *(uint32_t*)pL = lo;
}
__device__ __forceinline__ int wfrag_off(int n, int k, int NG) {
    int kt = k >> 4, ng = n >> 4, ntp = (n >> 3) & 1, gid = n & 7;
    int tig = (k >> 1) & 3, khalf = (k & 15) >> 3, par = k & 1;
    return kt * (NG * 512) + ng * 512 + (gid * 4 + tig) * 16 + ntp * 8 + khalf * 4 + par * 2;
}

#define XP 136
#define LP 68
#define O_XH   0
#define O_XL   34816
#define O_LAT  69632
#define SM_TOTAL 104448

extern __shared__ char smraw[];

template<int KT, int NG>
__device__ __forceinline__ void run_mma(const char* XHp, const char* XLp,
                                        const __nv_bfloat16* __restrict__ WH,
                                        const __nv_bfloat16* __restrict__ WL,
                                        float (&acc)[2*NG][4], int m0, int gid, int tig, int l) {
    #pragma unroll
    for (int kt = 0; kt < KT; kt++) {
        int k0 = kt * 16 + 2 * tig;
        const char* xa0 = XHp + ((m0 + gid) * XP + k0) * 2;
        const char* xa1 = XHp + ((m0 + gid + 8) * XP + k0) * 2;
        const char* xb0 = XLp + ((m0 + gid) * XP + k0) * 2;
        const char* xb1 = XLp + ((m0 + gid + 8) * XP + k0) * 2;
        uint32_t ah[4], al[4];
        ah[0] = *(const uint32_t*)xa0;        ah[1] = *(const uint32_t*)xa1;
        ah[2] = *(const uint32_t*)(xa0 + 16); ah[3] = *(const uint32_t*)(xa1 + 16);
        al[0] = *(const uint32_t*)xb0;        al[1] = *(const uint32_t*)xb1;
        al[2] = *(const uint32_t*)(xb0 + 16); al[3] = *(const uint32_t*)(xb1 + 16);
        #pragma unroll
        for (int ng = 0; ng < NG; ng++) {
            uint4 bh = __ldg((const uint4*)((const char*)WH + kt * (NG * 512) + ng * 512 + l * 16));
            uint4 bl = __ldg((const uint4*)((const char*)WL + kt * (NG * 512) + ng * 512 + l * 16));
            mma16816(acc[2 * ng],     ah, bh.x, bh.y);
            mma16816(acc[2 * ng],     ah, bl.x, bl.y);
            mma16816(acc[2 * ng],     al, bh.x, bh.y);
            mma16816(acc[2 * ng + 1], ah, bh.z, bh.w);
            mma16816(acc[2 * ng + 1], ah, bl.z, bl.w);
            mma16816(acc[2 * ng + 1], al, bh.z, bh.w);
        }
    }
}

// block exclusive scan for 256 threads (8 warps)
__device__ __forceinline__ uint blk_scan_excl(uint val, volatile uint* ws, uint* tot) {
    __syncthreads();
    int lane = threadIdx.x & 31, w = threadIdx.x >> 5;
    uint inc = val;
    #pragma unroll
    for (int o = 1; o < 32; o <<= 1) {
        uint x = __shfl_up_sync(0xffffffffu, inc, o);
        if (lane >= o) inc += x;
    }
    if (lane == 31) ws[w] = inc;
    __syncthreads();
    if (threadIdx.x == 0) {
        uint run = 0;
        for (int i = 0; i < 8; i++) { uint x = ws[i]; ws[i] = run; run += x; }
        ws[8] = run;
    }
    __syncthreads();
    if (tot) *tot = ws[8];
    return inc - val + ws[w];
}

// ---------------------------------------------------------------------------
// k_front: blocks [0,128) pack weights; [128,130) fold attention;
//          [130,1154) pre_h1 (16 rows each); [1154, 1154+8192) kNN.
// 256 threads, 36864 B dyn smem.
// ---------------------------------------------------------------------------
#define NB_PACK 128
#define NB_PREP 2
#define NB_H1   1024
#define KNN_BASE (NB_PACK + NB_PREP + NB_H1)

__global__ void __launch_bounds__(256) k_front(
    const float* __restrict__ nxw2, const float* __restrict__ nxw3,
    const float* __restrict__ sxw2, const float* __restrict__ sxw3,
    const float* __restrict__ att_w, const float* __restrict__ att_b,
    const float* __restrict__ att_q, const float* __restrict__ nxw1,
    const float* __restrict__ keys, const float* __restrict__ points,
    const float* __restrict__ feats)
{
    int tid = threadIdx.x;

    if (blockIdx.x < NB_PACK) {
        int t = blockIdx.x * 256 + tid;
        float v; int off; __nv_bfloat16 *dh, *dl;
        if (t < 16384) {
            int n = t >> 7, k = t & 127;
            v = nxw2[k * 128 + n]; off = wfrag_off(n, k, 8);
            dh = g_W2h; dl = g_W2l;
        } else if (t < 24576) {
            int i = t - 16384, n = i & 63, k = i >> 6;
            v = nxw3[k * 64 + n]; off = wfrag_off(n, k, 4);
            dh = g_W3h; dl = g_W3l;
        } else if (t < 28672) {
            int i = t - 24576, n = i & 63, k = i >> 6;
            v = sxw2[k * 64 + n]; off = wfrag_off(n, k, 4);
            dh = g_S2h; dl = g_S2l;
        } else {
            int i = t - 28672, n = i & 63, k = i >> 6;
            v = sxw3[k * 64 + n]; off = wfrag_off(n, k, 4);
            dh = g_S3h; dl = g_S3l;
        }
        __nv_bfloat16 hv = __float2bfloat16(v);
        __nv_bfloat16 lv = __float2bfloat16(v - __bfloat162float(hv));
        dh[off >> 1] = hv; dl[off >> 1] = lv;
        return;
    }
    if (blockIdx.x < NB_PACK + NB_PREP) {
        int t = (blockIdx.x - NB_PACK) * 256 + tid;   // 0..511
        if (t < 512) {
            int c = t >> 2, h = t & 3;
            float s = 0.f;
            #pragma unroll 8
            for (int o = 0; o < 64; o++) s += att_w[c * 256 + h * 64 + o] * att_q[h * 64 + o];
            g_A[t] = s;
        }
        if (t < 4) {
            float s = 0.f;
            #pragma unroll 8
            for (int o = 0; o < 64; o++) s += att_b[t * 64 + o] * att_q[t * 64 + o];
            g_A[512 + t] = s;
        }
        return;
    }
    if (blockIdx.x < KNN_BASE) {
        // pre_h1: 16 rows per block
        float* sw = (float*)smraw;        // [61*128]
        float* f  = sw + 7808;            // [16*61]
        int row0 = (blockIdx.x - NB_PACK - NB_PREP) * 16;
        for (int i = tid; i < 7808; i += 256) sw[i] = nxw1[384 + i];
        for (int i = tid; i < 976; i += 256) {
            int r = i / 61, c = i % 61;
            f[r * 61 + c] = feats[(size_t)(row0 + r) * 61 + c];
        }
        __syncthreads();
        int col = tid & 127, half = tid >> 7;
        #pragma unroll
        for (int r8 = 0; r8 < 8; r8++) {
            int r = half * 8 + r8;
            float acc = 0.f;
            #pragma unroll
            for (int c = 0; c < 61; c++) acc += f[r * 61 + c] * sw[c * 128 + col];
            g_h1pre[(size_t)(row0 + r) * 128 + col] = acc;
        }
        return;
    }

    // ------------------ kNN (256 threads, fused sweeps) ------------------
    uint* smu  = (uint*)smraw;
    uint* d2u  = smu;                                    // [4096]
    uint* hist = smu + 4096;                             // [2048]
    unsigned short* candP1 = (unsigned short*)(smu + 6144); // [3072]
    unsigned short* cand2  = candP1 + 3072;                 // [1024]

    __shared__ int  sel[KNBR];
    __shared__ uint ws[9];
    __shared__ int  sP1, sP2, sM2;
    __shared__ ull  wmin[8];

    int bk = blockIdx.x - KNN_BASE, b = bk >> 11, k = bk & 2047;

    float kx = keys[(b * KK + k) * 3 + 0];
    float ky = keys[(b * KK + k) * 3 + 1];
    float kz = keys[(b * KK + k) * 3 + 2];
    const float* pb = points + (size_t)b * NN * 3;

    #pragma unroll
    for (int j = 0; j < 8; j++) hist[tid + j * 256] = 0;
    __syncthreads();

    // sweep 1: distances + 11-bit histogram
    #pragma unroll
    for (int j = 0; j < 16; j++) {
        int p = tid + j * 256;
        float dx = pb[p * 3 + 0] - kx;
        float dy = pb[p * 3 + 1] - ky;
        float dz = pb[p * 3 + 2] - kz;
        uint u = __float_as_uint(dx * dx + dy * dy + dz * dz);
        d2u[p] = u;
        atomicAdd(&hist[u >> 21], 1u);
    }
    __syncthreads();

    // pass 1: find pivot bin P1 only
    {
        uint cnt8[8], s = 0;
        #pragma unroll
        for (int j = 0; j < 8; j++) { cnt8[j] = hist[tid * 8 + j]; s += cnt8[j]; }
        uint e = blk_scan_excl(s, ws, 0);
        if (e < KNBR && e + s >= KNBR) {
            uint cum = e;
            #pragma unroll
            for (int j = 0; j < 8; j++) {
                if (cum + cnt8[j] >= KNBR) { sP1 = tid * 8 + j; break; }
                cum += cnt8[j];
            }
        }
    }
    __syncthreads();
    int P1 = sP1;

    // sweep 2 (fused): below-P1 compaction + P1-candidate extraction + 8-bit hist
    hist[tid] = 0;
    __syncthreads();
    int m1;
    uint totP;
    {
        uint fb = 0, fp = 0;
        #pragma unroll
        for (int j = 0; j < 16; j++) {
            int p = tid + j * 256;
            uint u = d2u[p];
            int b1 = (int)(u >> 21);
            if (b1 < P1) fb |= (1u << j);
            else if (b1 == P1) {
                fp |= (1u << j);
                atomicAdd(&hist[(u >> 13) & 255], 1u);
            }
        }
        uint packed = ((uint)__popc(fb) << 16) | (uint)__popc(fp);
        uint tot;
        uint e = blk_scan_excl(packed, ws, &tot);
        int bB = (int)(e >> 16), bP = (int)(e & 0xFFFF);
        #pragma unroll
        for (int j = 0; j < 16; j++) {
            int p = tid + j * 256;
            if (fb & (1u << j)) sel[bB++] = p;
            if ((fp & (1u << j)) && bP < 3072) candP1[bP++] = (unsigned short)p;
        }
        m1 = (int)(tot >> 16);
        totP = tot & 0xFFFF;
        if (totP > 3072) totP = 3072;
    }
    __syncthreads();

    // find P2 within bin P1
    {
        uint v = hist[tid];
        uint e = blk_scan_excl(v, ws, 0);
        int need1 = KNBR - m1;
        if ((int)e < need1 && (int)(e + v) >= need1) { sP2 = tid; sM2 = (int)e; }
    }
    __syncthreads();
    int P2 = sP2, m2 = sM2;

    // classify small candP1 list: bin2<P2 -> sel, ==P2 -> cand2
    int cc;
    {
        uint fb2 = 0, fe2 = 0;
        int nIt = ((int)totP + 255) >> 8;
        for (int j = 0; j < nIt; j++) {
            int i = tid + j * 256;
            if (i < (int)totP) {
                int p = candP1[i];
                int b2 = (int)((d2u[p] >> 13) & 255);
                if (b2 < P2) fb2 |= (1u << j);
                else if (b2 == P2) fe2 |= (1u << j);
            }
        }
        uint packed = ((uint)__popc(fb2) << 16) | (uint)__popc(fe2);
        uint tot2;
        uint e = blk_scan_excl(packed, ws, &tot2);
        int bB = m1 + (int)(e >> 16), bE = (int)(e & 0xFFFF);
        for (int j = 0; j < nIt; j++) {
            int i = tid + j * 256;
            if (i < (int)totP) {
                int p = candP1[i];
                if (fb2 & (1u << j)) sel[bB++] = p;
                if ((fe2 & (1u << j)) && bE < 1024) cand2[bE++] = (unsigned short)p;
            }
        }
        cc = (int)(tot2 & 0xFFFF);
        if (cc > 1024) cc = 1024;
    }
    __syncthreads();

    // argmin rounds on boundary candidates
    {
        int m = m1 + m2, need = KNBR - m;
        for (int r = 0; r < need; r++) {
            ull best = ~0ull;
            for (int i = tid; i < cc; i += 256) {
                int p = cand2[i];
                ull key = ((ull)d2u[p] << 32) | (uint)p;
                if (key < best) best = key;
            }
            #pragma unroll
            for (int off = 16; off; off >>= 1) {
                ull o = __shfl_down_sync(0xffffffffu, best, off);
                if (o < best) best = o;
            }
            if ((tid & 31) == 0) wmin[tid >> 5] = best;
            __syncthreads();
            if (tid == 0) {
                ull bb = wmin[0];
                #pragma unroll
                for (int w = 1; w < 8; w++) if (wmin[w] < bb) bb = wmin[w];
                int p = (int)(bb & 0xFFFFFFFFull);
                sel[m + r] = p;
                d2u[p] = 0xFFFFFFFFu;
            }
            __syncthreads();
        }
    }

    // gather comb (reuse d2u as float cs[2048])
    float* cs = (float*)smu;
    const float* fb2g = feats + (size_t)b * NN * CIN;
    __syncthreads();
    #pragma unroll
    for (int j = 0; j < 8; j++) {
        int e = tid + j * 256;
        int n = e >> 6, c = e & 63;
        int p = sel[n];
        float v;
        if (c < 3) {
            float kc = (c == 0) ? kx : ((c == 1) ? ky : kz);
            v = pb[p * 3 + c] - kc;
        } else v = fb2g[p * CIN + (c - 3)];
        cs[e] = v;
    }
    __syncthreads();

    if (tid < 64) {
        float s = 0.f, ss = 0.f;
        #pragma unroll
        for (int n = 0; n < KNBR; n++) { float v = cs[n * 64 + tid]; s += v; ss += v * v; }
        g_part[(size_t)tid * NBK + bk]        = s;
        g_part[(size_t)(64 + tid) * NBK + bk] = ss;
    }
    if (tid < 32) g_selg[(size_t)bk * 32 + tid] = b * NN + sel[tid];
    if (tid < 96) g_rel[(size_t)bk * 96 + tid] = cs[(tid / 3) * 64 + (tid % 3)];
}

// ---------------------------------------------------------------------------
__global__ void __launch_bounds__(256) k_stats(const float* __restrict__ gamma,
                                               const float* __restrict__ beta) {
    int c = blockIdx.x, t = threadIdx.x;
    double s = 0.0, ss = 0.0;
    const float4* ps  = (const float4*)(g_part + (size_t)c * NBK);
    const float4* pss = (const float4*)(g_part + (size_t)(64 + c) * NBK);
    for (int i = t; i < NBK / 4; i += 256) {
        float4 a = ps[i], bq = pss[i];
        s  += (double)a.x + (double)a.y + (double)a.z + (double)a.w;
        ss += (double)bq.x + (double)bq.y + (double)bq.z + (double)bq.w;
    }
    __shared__ double rs[256], rss[256];
    rs[t] = s; rss[t] = ss;
    __syncthreads();
    for (int o = 128; o; o >>= 1) {
        if (t < o) { rs[t] += rs[t + o]; rss[t] += rss[t + o]; }
        __syncthreads();
    }
    if (t == 0) {
        double mean = rs[0] / CNTF;
        double var  = rss[0] / CNTF - mean * mean;
        float sc = (float)((1.0 / sqrt(var + 1e-5)) * (double)gamma[c]);
        g_sc[c] = sc;
        g_tc[c] = beta[c] - (float)mean * sc;
    }
}

// ---------------------------------------------------------------------------
// k_mid: block 0 = const folding; blocks 1..1024 = pre_s1e (16 rows each)
// ---------------------------------------------------------------------------
__global__ void __launch_bounds__(256) k_mid(const float* __restrict__ sxw1,
                                             const float* __restrict__ sxb1,
                                             const float* __restrict__ feats) {
    __shared__ float sw[61 * 64];
    __shared__ float sa[244];
    __shared__ float sf[16 * 61];
    int t = threadIdx.x;

    if (blockIdx.x == 0) {
        if (t < 64) {
            float s = sxb1[t];
            #pragma unroll 8
            for (int c = 0; c < 64; c++) s += g_tc[c] * sxw1[c * 64 + t];
            g_C1[t] = s;
        }
        if (t < 4) {
            float s = g_A[512 + t];
            #pragma unroll 8
            for (int c = 0; c < 64; c++) s += g_tc[c] * g_A[c * 4 + t];
            g_Ce[t] = s;
        }
        if (t >= 64) {
            int i = t - 64, c = i >> 6, o = i & 63;
            g_Wr1s[i] = g_sc[c] * sxw1[c * 64 + o];
        }
        if (t < 12) g_A1s[t] = g_sc[t >> 2] * g_A[(t >> 2) * 4 + (t & 3)];
        return;
    }

    int row0 = (blockIdx.x - 1) * 16;
    for (int i = t; i < 61 * 64; i += 256) {
        int c = i >> 6, o = i & 63;
        sw[i] = sxw1[(3 + c) * 64 + o];
    }
    if (t < 244) sa[t] = g_A[12 + t];
    for (int i = t; i < 976; i += 256) {
        int r = i / 61, c = i % 61;
        sf[r * 61 + c] = feats[(size_t)(row0 + r) * 61 + c] * g_sc[3 + c];
    }
    __syncthreads();
    int o = t & 63, rg = t >> 6;
    #pragma unroll
    for (int rr = 0; rr < 4; rr++) {
        int r = rg * 4 + rr;
        float acc = 0.f;
        #pragma unroll
        for (int c = 0; c < 61; c++) acc += sf[r * 61 + c] * sw[(c << 6) + o];
        g_s1pre[(size_t)(row0 + r) * 64 + o] = acc;
    }
    if (t < 64) {
        int r = t >> 2, h = t & 3;
        float s = 0.f;
        #pragma unroll
        for (int c = 0; c < 61; c++) s += sf[r * 61 + c] * sa[c * 4 + h];
        g_epre[(size_t)(row0 + r) * 4 + h] = s;
    }
}

// ---------------------------------------------------------------------------
// k_main: unchanged (verified 390 µs config).
// ---------------------------------------------------------------------------
__global__ void __launch_bounds__(256, 2) k_main(
    const float* __restrict__ nxw1, const float* __restrict__ nxb1,
    const float* __restrict__ nxb2, const float* __restrict__ nxb3,
    const float* __restrict__ sxb2, const float* __restrict__ sxb3,
    float* __restrict__ out)
{
    char* XH  = smraw + O_XH;
    char* XL  = smraw + O_XL;
    float* LAT = (float*)(smraw + O_LAT);

    __shared__ int   sel_s[128];
    __shared__ float rel_s[384];
    __shared__ float setp[8][64];
    __shared__ float gh[16];
    __shared__ float ebuf[512];
    __shared__ float wbuf[512];

    int t = threadIdx.x, w = t >> 5, l = t & 31;
    int gid = l >> 2, tig = l & 3;
    int m0 = w * 16;
    int bk0 = blockIdx.x * 4;

    if (t < 128) sel_s[t] = g_selg[(size_t)bk0 * 32 + t];
    for (int i = t; i < 384; i += 256) rel_s[i] = g_rel[(size_t)bk0 * 96 + i];
    __syncthreads();

    // Stage A
    #pragma unroll 4
    for (int i = 0; i < 32; i++) {
        int e = i * 32 + l;
        int r = e >> 6, c2 = (e & 63) * 2;
        int m = m0 + r;
        int q = m >> 5, nn = m & 31;
        float rx = rel_s[q * 96 + nn * 3], ry = rel_s[q * 96 + nn * 3 + 1], rz = rel_s[q * 96 + nn * 3 + 2];
        float2 hp = *(const float2*)(g_h1pre + (size_t)sel_s[m] * 128 + c2);
        float2 b1 = *(const float2*)(nxb1 + c2);
        float2 w0 = *(const float2*)(nxw1 + c2);
        float2 w1 = *(const float2*)(nxw1 + 128 + c2);
        float2 w2 = *(const float2*)(nxw1 + 256 + c2);
        float v0 = fmaxf(hp.x + b1.x + rx * w0.x + ry * w1.x + rz * w2.x, 0.f);
        float v1 = fmaxf(hp.y + b1.y + rx * w0.y + ry * w1.y + rz * w2.y, 0.f);
        split_store(v0, v1, XH + (m * XP + c2) * 2, XL + (m * XP + c2) * 2);
    }
    __syncwarp();

    // Stage B
    {
        float acc[16][4];
        #pragma unroll
        for (int nt = 0; nt < 16; nt++)
            #pragma unroll
            for (int j = 0; j < 4; j++) acc[nt][j] = 0.f;
        run_mma<8, 8>(XH, XL, g_W2h, g_W2l, acc, m0, gid, tig, l);
        #pragma unroll
        for (int nt = 0; nt < 16; nt++) {
            int cb = nt * 8 + 2 * tig;
            float2 bb = *(const float2*)(nxb2 + cb);
            int r0 = m0 + gid, r1 = r0 + 8;
            split_store(fmaxf(acc[nt][0] + bb.x, 0.f), fmaxf(acc[nt][1] + bb.y, 0.f),
                        XH + (r0 * XP + cb) * 2, XL + (r0 * XP + cb) * 2);
            split_store(fmaxf(acc[nt][2] + bb.x, 0.f), fmaxf(acc[nt][3] + bb.y, 0.f),
                        XH + (r1 * XP + cb) * 2, XL + (r1 * XP + cb) * 2);
        }
    }
    __syncwarp();

    // Stage C
    {
        float acc[8][4];
        #pragma unroll
        for (int nt = 0; nt < 8; nt++)
            #pragma unroll
            for (int j = 0; j < 4; j++) acc[nt][j] = 0.f;
        run_mma<8, 4>(XH, XL, g_W3h, g_W3l, acc, m0, gid, tig, l);
        #pragma unroll
        for (int nt = 0; nt < 8; nt++) {
            int cb = nt * 8 + 2 * tig;
            float2 bb = *(const float2*)(nxb3 + cb);
            int r0 = m0 + gid, r1 = r0 + 8;
            *(float2*)(LAT + r0 * LP + cb) = make_float2(acc[nt][0] + bb.x, acc[nt][1] + bb.y);
            *(float2*)(LAT + r1 * LP + cb) = make_float2(acc[nt][2] + bb.x, acc[nt][3] + bb.y);
        }
    }
    __syncwarp();

    // Stage D
    #pragma unroll 4
    for (int i = 0; i < 16; i++) {
        int e = i * 32 + l;
        int r = e >> 5, c2 = (e & 31) * 2;
        int m = m0 + r;
        int q = m >> 5, nn = m & 31;
        float rx = rel_s[q * 96 + nn * 3], ry = rel_s[q * 96 + nn * 3 + 1], rz = rel_s[q * 96 + nn * 3 + 2];
        float2 sp = *(const float2*)(g_s1pre + (size_t)sel_s[m] * 64 + c2);
        float2 c1 = *(const float2*)(g_C1 + c2);
        float2 w0 = *(const float2*)(g_Wr1s + c2);
        float2 w1 = *(const float2*)(g_Wr1s + 64 + c2);
        float2 w2 = *(const float2*)(g_Wr1s + 128 + c2);
        float v0 = fmaxf(sp.x + c1.x + rx * w0.x + ry * w1.x + rz * w2.x, 0.f);
        float v1 = fmaxf(sp.y + c1.y + rx * w0.y + ry * w1.y + rz * w2.y, 0.f);
        split_store(v0, v1, XH + (m * XP + c2) * 2, XL + (m * XP + c2) * 2);
    }
    __syncwarp();

    // Stage E
    {
        float acc[8][4];
        #pragma unroll
        for (int nt = 0; nt < 8; nt++)
            #pragma unroll
            for (int j = 0; j < 4; j++) acc[nt][j] = 0.f;
        run_mma<4, 4>(XH, XL, g_S2h, g_S2l, acc, m0, gid, tig, l);
        #pragma unroll
        for (int nt = 0; nt < 8; nt++) {
            int cb = nt * 8 + 2 * tig;
            float2 bb = *(const float2*)(sxb2 + cb);
            int r0 = m0 + gid, r1 = r0 + 8;
            split_store(fmaxf(acc[nt][0] + bb.x, 0.f), fmaxf(acc[nt][1] + bb.y, 0.f),
                        XH + (r0 * XP + cb) * 2, XL + (r0 * XP + cb) * 2);
            split_store(fmaxf(acc[nt][2] + bb.x, 0.f), fmaxf(acc[nt][3] + bb.y, 0.f),
                        XH + (r1 * XP + cb) * 2, XL + (r1 * XP + cb) * 2);
        }
    }
    __syncwarp();

    // Stage F
    {
        float acc[8][4];
        #pragma unroll
        for (int nt = 0; nt < 8; nt++)
            #pragma unroll
            for (int j = 0; j < 4; j++) acc[nt][j] = 0.f;
        run_mma<4, 4>(XH, XL, g_S3h, g_S3l, acc, m0, gid, tig, l);
        #pragma unroll
        for (int nt = 0; nt < 8; nt++) {
            float v0 = acc[nt][0] + acc[nt][2];
            float v1 = acc[nt][1] + acc[nt][3];
            #pragma unroll
            for (int off = 16; off >= 4; off >>= 1) {
                v0 += __shfl_down_sync(0xffffffffu, v0, off);
                v1 += __shfl_down_sync(0xffffffffu, v1, off);
            }
            if (gid == 0) {
                int cb = nt * 8 + 2 * tig;
                setp[w][cb] = v0;
                setp[w][cb + 1] = v1;
            }
        }
    }
    __syncthreads();

    if (t < 16) {
        int q = t >> 2, h = t & 3;
        float s = g_Ce[h];
        #pragma unroll 8
        for (int c = 0; c < 64; c++) {
            float sf = setp[2 * q][c] + setp[2 * q + 1][c] + 32.f * sxb3[c];
            s += sf * g_A[(64 + c) * 4 + h];
        }
        gh[t] = s;
    }
    __syncthreads();
    #pragma unroll
    for (int r = 0; r < 2; r++) {
        int idx = t + r * 256;
        int q = idx >> 7, i2 = idx & 127, n = i2 >> 2, h = i2 & 3;
        int gn = q * 32 + n;
        ebuf[idx] = gh[q * 4 + h] + g_epre[(size_t)sel_s[gn] * 4 + h]
                  + rel_s[q * 96 + n * 3]     * g_A1s[h]
                  + rel_s[q * 96 + n * 3 + 1] * g_A1s[4 + h]
                  + rel_s[q * 96 + n * 3 + 2] * g_A1s[8 + h];
    }
    __syncthreads();
    if (t < 16) {
        int q = t >> 2, h = t & 3;
        float mx = -INFINITY;
        #pragma unroll
        for (int n = 0; n < 32; n++) mx = fmaxf(mx, ebuf[q * 128 + n * 4 + h]);
        float s = 0.f;
        #pragma unroll
        for (int n = 0; n < 32; n++) {
            float ex = expf(ebuf[q * 128 + n * 4 + h] - mx);
            wbuf[q * 128 + n * 4 + h] = ex;
            s += ex;
        }
        float inv = 1.f / s;
        #pragma unroll
        for (int n = 0; n < 32; n++) wbuf[q * 128 + n * 4 + h] *= inv;
    }
    __syncthreads();
    #pragma unroll
    for (int r = 0; r < 4; r++) {
        int idx = t + r * 256;
        int q = idx >> 8, i2 = idx & 255, o = i2 >> 2, h = i2 & 3;
        float s = 0.f;
        #pragma unroll
        for (int n = 0; n < 32; n++)
            s += LAT[(q * 32 + n) * LP + o] * wbuf[q * 128 + n * 4 + h];
        out[(size_t)(bk0 + q) * 256 + i2] = s;
    }
}

// ---------------------------------------------------------------------------
extern "C" void kernel_launch(void* const* d_in, const int* in_sizes, int n_in,
                              void* d_out, int out_size) {
    (void)in_sizes; (void)n_in; (void)out_size;
    const float* keys  = (const float*)d_in[0];
    const float* points= (const float*)d_in[1];
    const float* feats = (const float*)d_in[2];
    const float* nxw1  = (const float*)d_in[3];
    const float* nxb1  = (const float*)d_in[4];
    const float* nxw2  = (const float*)d_in[5];
    const float* nxb2  = (const float*)d_in[6];
    const float* nxw3  = (const float*)d_in[7];
    const float* nxb3  = (const float*)d_in[8];
    const float* sxw1  = (const float*)d_in[9];
    const float* sxb1  = (const float*)d_in[10];
    const float* sxw2  = (const float*)d_in[11];
    const float* sxb2  = (const float*)d_in[12];
    const float* sxw3  = (const float*)d_in[13];
    const float* sxb3  = (const float*)d_in[14];
    const float* attw  = (const float*)d_in[15];
    const float* attb  = (const float*)d_in[16];
    const float* attq  = (const float*)d_in[17];
    const float* gamma = (const float*)d_in[18];
    const float* beta  = (const float*)d_in[19];
    float* out = (float*)d_out;

    cudaFuncSetAttribute(k_main, cudaFuncAttributeMaxDynamicSharedMemorySize, SM_TOTAL);

    k_front<<<KNN_BASE + NBK, 256, 36864>>>(nxw2, nxw3, sxw2, sxw3,
                                            attw, attb, attq, nxw1,
                                            keys, points, feats);
    k_stats<<<64, 256>>>(gamma, beta);
    k_mid<<<1025, 256>>>(sxw1, sxb1, feats);
    k_main<<<NBK / 4, 256, SM_TOTAL>>>(nxw1, nxb1, nxb2, nxb3, sxb2, sxb3, out);
}

// round 15
// speedup vs baseline: 1.1196x; 1.1196x over previous
#include <cuda_runtime.h>
#include <cuda_bf16.h>
#include <math.h>
#include <stdint.h>

#define BB 4
#define KK 2048
#define NN 4096
#define CIN 61
#define NBK (BB*KK)
#define NPTS (BB*NN)
#define KNBR 32
#define CNTF 262144.0

typedef unsigned long long ull;

// ---------------- scratch globals ----------------
__device__ float g_part[(size_t)128 * NBK];
__device__ float g_A[516];
__device__ int   g_selg[(size_t)NBK * KNBR];
__device__ float g_rel[(size_t)NBK * KNBR * 3];
__device__ float g_h1pre[(size_t)NPTS * 128];
__device__ float g_s1pre[(size_t)NPTS * 64];
__device__ float g_epre[(size_t)NPTS * 4];
__device__ float g_sc[64], g_tc[64];
__device__ float g_C1[64], g_Ce[4];
__device__ float g_Wr1s[192], g_A1s[12];
// fragment-packed bf16 weights (hi/lo)
__device__ __align__(16) __nv_bfloat16 g_W2h[16384], g_W2l[16384];
__device__ __align__(16) __nv_bfloat16 g_W3h[8192],  g_W3l[8192];
__device__ __align__(16) __nv_bfloat16 g_S2h[4096],  g_S2l[4096];
__device__ __align__(16) __nv_bfloat16 g_S3h[4096],  g_S3l[4096];

// ---------------- helpers ----------------
__device__ __forceinline__ void mma16816(float* d, const uint32_t* a, uint32_t b0, uint32_t b1) {
    asm volatile("mma.sync.aligned.m16n8k16.row.col.f32.bf16.bf16.f32 "
        "{%0,%1,%2,%3}, {%4,%5,%6,%7}, {%8,%9}, {%0,%1,%2,%3};"
        : "+f"(d[0]), "+f"(d[1]), "+f"(d[2]), "+f"(d[3])
        : "r"(a[0]), "r"(a[1]), "r"(a[2]), "r"(a[3]), "r"(b0), "r"(b1));
}
__device__ __forceinline__ void split_store(float v0, float v1, char* pH, char* pL) {
    uint32_t h;
    asm("cvt.rn.bf16x2.f32 %0, %1, %2;" : "=r"(h) : "f"(v1), "f"(v0));
    float r0 = v0 - __uint_as_float(h << 16);
    float r1 = v1 - __uint_as_float(h & 0xFFFF0000u);
    uint32_t lo;
    asm("cvt.rn.bf16x2.f32 %0, %1, %2;" : "=r"(lo) : "f"(r1), "f"(r0));
    *(uint32_t*)pH = h;
    *(uint32_t*)pL = lo;
}
__device__ __forceinline__ int wfrag_off(int n, int k, int NG) {
    int kt = k >> 4, ng = n >> 4, ntp = (n >> 3) & 1, gid = n & 7;
    int tig = (k >> 1) & 3, khalf = (k & 15) >> 3, par = k & 1;
    return kt * (NG * 512) + ng * 512 + (gid * 4 + tig) * 16 + ntp * 8 + khalf * 4 + par * 2;
}

#define XP 136
#define LP 68
#define O_XH   0
#define O_XL   34816
#define O_LAT  69632
#define SM_TOTAL 104448

extern __shared__ char smraw[];

template<int KT, int NG>
__device__ __forceinline__ void run_mma(const char* XHp, const char* XLp,
                                        const __nv_bfloat16* __restrict__ WH,
                                        const __nv_bfloat16* __restrict__ WL,
                                        float (&acc)[2*NG][4], int m0, int gid, int tig, int l) {
    #pragma unroll
    for (int kt = 0; kt < KT; kt++) {
        int k0 = kt * 16 + 2 * tig;
        const char* xa0 = XHp + ((m0 + gid) * XP + k0) * 2;
        const char* xa1 = XHp + ((m0 + gid + 8) * XP + k0) * 2;
        const char* xb0 = XLp + ((m0 + gid) * XP + k0) * 2;
        const char* xb1 = XLp + ((m0 + gid + 8) * XP + k0) * 2;
        uint32_t ah[4], al[4];
        ah[0] = *(const uint32_t*)xa0;        ah[1] = *(const uint32_t*)xa1;
        ah[2] = *(const uint32_t*)(xa0 + 16); ah[3] = *(const uint32_t*)(xa1 + 16);
        al[0] = *(const uint32_t*)xb0;        al[1] = *(const uint32_t*)xb1;
        al[2] = *(const uint32_t*)(xb0 + 16); al[3] = *(const uint32_t*)(xb1 + 16);
        #pragma unroll
        for (int ng = 0; ng < NG; ng++) {
            uint4 bh = __ldg((const uint4*)((const char*)WH + kt * (NG * 512) + ng * 512 + l * 16));
            uint4 bl = __ldg((const uint4*)((const char*)WL + kt * (NG * 512) + ng * 512 + l * 16));
            mma16816(acc[2 * ng],     ah, bh.x, bh.y);
            mma16816(acc[2 * ng],     ah, bl.x, bl.y);
            mma16816(acc[2 * ng],     al, bh.x, bh.y);
            mma16816(acc[2 * ng + 1], ah, bh.z, bh.w);
            mma16816(acc[2 * ng + 1], ah, bl.z, bl.w);
            mma16816(acc[2 * ng + 1], al, bh.z, bh.w);
        }
    }
}

// ---------------------------------------------------------------------------
__global__ void k_prep(const float* __restrict__ att_w, const float* __restrict__ att_b,
                       const float* __restrict__ att_q) {
    int t = blockIdx.x * blockDim.x + threadIdx.x;
    if (t < 512) {
        int c = t >> 2, h = t & 3;
        float s = 0.f;
        #pragma unroll 8
        for (int o = 0; o < 64; o++) s += att_w[c * 256 + h * 64 + o] * att_q[h * 64 + o];
        g_A[t] = s;
    }
    if (t < 4) {
        float s = 0.f;
        #pragma unroll 8
        for (int o = 0; o < 64; o++) s += att_b[t * 64 + o] * att_q[t * 64 + o];
        g_A[512 + t] = s;
    }
}

__global__ void __launch_bounds__(256) k_packw(const float* __restrict__ nxw2,
                                               const float* __restrict__ nxw3,
                                               const float* __restrict__ sxw2,
                                               const float* __restrict__ sxw3) {
    int t = blockIdx.x * blockDim.x + threadIdx.x;
    float v; int off; __nv_bfloat16 *dh, *dl;
    if (t < 16384) {
        int n = t >> 7, k = t & 127;
        v = nxw2[k * 128 + n]; off = wfrag_off(n, k, 8);
        dh = g_W2h; dl = g_W2l;
    } else if (t < 24576) {
        int i = t - 16384, n = i & 63, k = i >> 6;
        v = nxw3[k * 64 + n]; off = wfrag_off(n, k, 4);
        dh = g_W3h; dl = g_W3l;
    } else if (t < 28672) {
        int i = t - 24576, n = i & 63, k = i >> 6;
        v = sxw2[k * 64 + n]; off = wfrag_off(n, k, 4);
        dh = g_S2h; dl = g_S2l;
    } else {
        int i = t - 28672, n = i & 63, k = i >> 6;
        v = sxw3[k * 64 + n]; off = wfrag_off(n, k, 4);
        dh = g_S3h; dl = g_S3l;
    }
    __nv_bfloat16 hv = __float2bfloat16(v);
    __nv_bfloat16 lv = __float2bfloat16(v - __bfloat162float(hv));
    dh[off >> 1] = hv; dl[off >> 1] = lv;
}

// 8 rows per block, nxw1 feats-part staged in smem (verified in R12 @390µs)
__global__ void __launch_bounds__(128) k_pre_h1(const float* __restrict__ feats,
                                                const float* __restrict__ nxw1) {
    __shared__ float sw[61 * 128];
    __shared__ float f[8][61];
    int t = threadIdx.x;
    int row0 = blockIdx.x * 8;
    for (int i = t; i < 61 * 128; i += 128) sw[i] = nxw1[384 + i];
    for (int i = t; i < 8 * 61; i += 128) {
        int r = i / 61, c = i % 61;
        f[r][c] = feats[(size_t)(row0 + r) * 61 + c];
    }
    __syncthreads();
    #pragma unroll
    for (int r = 0; r < 8; r++) {
        float acc = 0.f;
        #pragma unroll
        for (int c = 0; c < 61; c++) acc += f[r][c] * sw[c * 128 + t];
        g_h1pre[(size_t)(row0 + r) * 128 + t] = acc;
    }
}

// block exclusive scan (256 threads)
__device__ __forceinline__ uint blk_scan_excl(uint val, volatile uint* ws, uint* tot) {
    __syncthreads();
    int lane = threadIdx.x & 31, w = threadIdx.x >> 5;
    uint inc = val;
    #pragma unroll
    for (int o = 1; o < 32; o <<= 1) {
        uint x = __shfl_up_sync(0xffffffffu, inc, o);
        if (lane >= o) inc += x;
    }
    if (lane == 31) ws[w] = inc;
    __syncthreads();
    if (threadIdx.x == 0) {
        uint run = 0;
        for (int i = 0; i < 8; i++) { uint x = ws[i]; ws[i] = run; run += x; }
        ws[8] = run;
    }
    __syncthreads();
    if (tot) *tot = ws[8];
    return inc - val + ws[w];
}

// ---------------------------------------------------------------------------
// kNN: verified fastest variant (R7 profile: 97.7µs) — 256 threads, scalar
// loads, radix-select. dyn smem 32KB.
// ---------------------------------------------------------------------------
__global__ void __launch_bounds__(256) k_knn(const float* __restrict__ keys,
                                             const float* __restrict__ points,
                                             const float* __restrict__ feats) {
    uint* smu  = (uint*)smraw;
    uint* d2u  = smu;
    uint* hist = smu + 4096;
    unsigned short* cand = (unsigned short*)(smu + 6144);

    __shared__ int  sel[KNBR];
    __shared__ uint ws[9];
    __shared__ int  sP1, sM1, sP2, sM2;
    __shared__ ull  wmin[8];

    int bk = blockIdx.x, b = bk >> 11, k = bk & 2047, tid = threadIdx.x;

    float kx = keys[(b * KK + k) * 3 + 0];
    float ky = keys[(b * KK + k) * 3 + 1];
    float kz = keys[(b * KK + k) * 3 + 2];
    const float* pb = points + (size_t)b * NN * 3;

    #pragma unroll
    for (int j = 0; j < 8; j++) hist[tid + j * 256] = 0;
    __syncthreads();

    #pragma unroll
    for (int j = 0; j < 16; j++) {
        int p = tid + j * 256;
        float dx = pb[p * 3 + 0] - kx;
        float dy = pb[p * 3 + 1] - ky;
        float dz = pb[p * 3 + 2] - kz;
        uint u = __float_as_uint(dx * dx + dy * dy + dz * dz);
        d2u[p] = u;
        atomicAdd(&hist[u >> 21], 1u);
    }
    __syncthreads();

    // pass 1: find 11-bit pivot bin
    {
        uint cnt8[8], s = 0;
        #pragma unroll
        for (int j = 0; j < 8; j++) { cnt8[j] = hist[tid * 8 + j]; s += cnt8[j]; }
        uint e = blk_scan_excl(s, ws, 0);
        if (e < KNBR && e + s >= KNBR) {
            uint cum = e;
            #pragma unroll
            for (int j = 0; j < 8; j++) {
                if (cum + cnt8[j] >= KNBR) { sP1 = tid * 8 + j; sM1 = (int)cum; break; }
                cum += cnt8[j];
            }
        }
    }
    __syncthreads();
    int P1 = sP1, m1 = sM1;

    // pass 2: 8-bit refine inside bin P1
    hist[tid] = 0;
    __syncthreads();
    #pragma unroll
    for (int j = 0; j < 16; j++) {
        int p = tid + j * 256;
        uint u = d2u[p];
        if ((int)(u >> 21) == P1) atomicAdd(&hist[(u >> 13) & 255], 1u);
    }
    __syncthreads();
    {
        uint v = hist[tid];
        uint e = blk_scan_excl(v, ws, 0);
        int need1 = KNBR - m1;
        if ((int)e < need1 && (int)(e + v) >= need1) { sP2 = tid; sM2 = (int)e; }
    }
    __syncthreads();
    int P2 = sP2, m2 = sM2;

    // compaction: strictly-below -> sel, boundary -> cand
    uint tot = 0;
    {
        uint fb = 0, fe = 0;
        #pragma unroll
        for (int j = 0; j < 16; j++) {
            int p = tid + j * 256;
            uint u = d2u[p];
            int b1 = (int)(u >> 21);
            if (b1 < P1) fb |= (1u << j);
            else if (b1 == P1) {
                int b2 = (int)((u >> 13) & 255);
                if (b2 < P2) fb |= (1u << j);
                else if (b2 == P2) fe |= (1u << j);
            }
        }
        uint packed = ((uint)__popc(fb) << 16) | (uint)__popc(fe);
        uint e = blk_scan_excl(packed, ws, &tot);
        int bB = (int)(e >> 16), bE = (int)(e & 0xFFFF);
        #pragma unroll
        for (int j = 0; j < 16; j++) {
            int p = tid + j * 256;
            if (fb & (1u << j)) sel[bB++] = p;
            if (fe & (1u << j)) cand[bE++] = (unsigned short)p;
        }
    }
    __syncthreads();

    // argmin rounds on boundary candidates
    {
        int m = m1 + m2, need = KNBR - m, cc = (int)(tot & 0xFFFF);
        for (int r = 0; r < need; r++) {
            ull best = ~0ull;
            for (int i = tid; i < cc; i += 256) {
                int p = cand[i];
                ull key = ((ull)d2u[p] << 32) | (uint)p;
                if (key < best) best = key;
            }
            #pragma unroll
            for (int off = 16; off; off >>= 1) {
                ull o = __shfl_down_sync(0xffffffffu, best, off);
                if (o < best) best = o;
            }
            if ((tid & 31) == 0) wmin[tid >> 5] = best;
            __syncthreads();
            if (tid == 0) {
                ull bb = wmin[0];
                #pragma unroll
                for (int w = 1; w < 8; w++) if (wmin[w] < bb) bb = wmin[w];
                int p = (int)(bb & 0xFFFFFFFFull);
                sel[m + r] = p;
                d2u[p] = 0xFFFFFFFFu;
            }
            __syncthreads();
        }
    }

    // gather comb (reuse d2u region as float cs[2048])
    float* cs = (float*)smu;
    const float* fb2 = feats + (size_t)b * NN * CIN;
    __syncthreads();
    #pragma unroll
    for (int j = 0; j < 8; j++) {
        int e = tid + j * 256;
        int n = e >> 6, c = e & 63;
        int p = sel[n];
        float v;
        if (c < 3) {
            float kc = (c == 0) ? kx : ((c == 1) ? ky : kz);
            v = pb[p * 3 + c] - kc;
        } else v = fb2[p * CIN + (c - 3)];
        cs[e] = v;
    }
    __syncthreads();

    if (tid < 64) {
        float s = 0.f, ss = 0.f;
        #pragma unroll
        for (int n = 0; n < KNBR; n++) { float v = cs[n * 64 + tid]; s += v; ss += v * v; }
        g_part[(size_t)tid * NBK + bk]        = s;
        g_part[(size_t)(64 + tid) * NBK + bk] = ss;
    }
    if (tid < 32) g_selg[(size_t)bk * 32 + tid] = b * NN + sel[tid];
    if (tid < 96) g_rel[(size_t)bk * 96 + tid] = cs[(tid / 3) * 64 + (tid % 3)];
}

// ---------------------------------------------------------------------------
__global__ void __launch_bounds__(256) k_stats(const float* __restrict__ gamma,
                                               const float* __restrict__ beta) {
    int c = blockIdx.x, t = threadIdx.x;
    double s = 0.0, ss = 0.0;
    const float4* ps  = (const float4*)(g_part + (size_t)c * NBK);
    const float4* pss = (const float4*)(g_part + (size_t)(64 + c) * NBK);
    for (int i = t; i < NBK / 4; i += 256) {
        float4 a = ps[i], bq = pss[i];
        s  += (double)a.x + (double)a.y + (double)a.z + (double)a.w;
        ss += (double)bq.x + (double)bq.y + (double)bq.z + (double)bq.w;
    }
    __shared__ double rs[256], rss[256];
    rs[t] = s; rss[t] = ss;
    __syncthreads();
    for (int o = 128; o; o >>= 1) {
        if (t < o) { rs[t] += rs[t + o]; rss[t] += rss[t + o]; }
        __syncthreads();
    }
    if (t == 0) {
        double mean = rs[0] / CNTF;
        double var  = rss[0] / CNTF - mean * mean;
        float sc = (float)((1.0 / sqrt(var + 1e-5)) * (double)gamma[c]);
        g_sc[c] = sc;
        g_tc[c] = beta[c] - (float)mean * sc;
    }
}

__global__ void k_const(const float* __restrict__ sxw1, const float* __restrict__ sxb1) {
    int t = threadIdx.x;
    if (t < 64) {
        float s = sxb1[t];
        #pragma unroll 8
        for (int c = 0; c < 64; c++) s += g_tc[c] * sxw1[c * 64 + t];
        g_C1[t] = s;
    }
    if (t < 4) {
        float s = g_A[512 + t];
        #pragma unroll 8
        for (int c = 0; c < 64; c++) s += g_tc[c] * g_A[c * 4 + t];
        g_Ce[t] = s;
    }
    if (t >= 64) {
        int i = t - 64, c = i >> 6, o = i & 63;
        g_Wr1s[i] = g_sc[c] * sxw1[c * 64 + o];
    }
    if (t < 12) g_A1s[t] = g_sc[t >> 2] * g_A[(t >> 2) * 4 + (t & 3)];
}

__global__ void __launch_bounds__(64) k_pre_s1e(const float* __restrict__ feats,
                                                const float* __restrict__ sxw1) {
    int row = blockIdx.x, t = threadIdx.x;
    __shared__ float sf[61];
    if (t < 61) sf[t] = feats[(size_t)row * 61 + t] * g_sc[3 + t];
    __syncthreads();
    float acc = 0.f;
    #pragma unroll
    for (int c = 0; c < 61; c++) acc += sf[c] * sxw1[(3 + c) * 64 + t];
    g_s1pre[(size_t)row * 64 + t] = acc;
    if (t < 4) {
        float s = 0.f;
        #pragma unroll
        for (int c = 0; c < 61; c++) s += sf[c] * g_A[(3 + c) * 4 + t];
        g_epre[(size_t)row * 4 + t] = s;
    }
}

// ---------------------------------------------------------------------------
// k_main: unchanged verified config (230.9µs measured; 82% of HMMA floor).
// ---------------------------------------------------------------------------
__global__ void __launch_bounds__(256, 2) k_main(
    const float* __restrict__ nxw1, const float* __restrict__ nxb1,
    const float* __restrict__ nxb2, const float* __restrict__ nxb3,
    const float* __restrict__ sxb2, const float* __restrict__ sxb3,
    float* __restrict__ out)
{
    char* XH  = smraw + O_XH;
    char* XL  = smraw + O_XL;
    float* LAT = (float*)(smraw + O_LAT);

    __shared__ int   sel_s[128];
    __shared__ float rel_s[384];
    __shared__ float setp[8][64];
    __shared__ float gh[16];
    __shared__ float ebuf[512];
    __shared__ float wbuf[512];

    int t = threadIdx.x, w = t >> 5, l = t & 31;
    int gid = l >> 2, tig = l & 3;
    int m0 = w * 16;
    int bk0 = blockIdx.x * 4;

    if (t < 128) sel_s[t] = g_selg[(size_t)bk0 * 32 + t];
    for (int i = t; i < 384; i += 256) rel_s[i] = g_rel[(size_t)bk0 * 96 + i];
    __syncthreads();

    // Stage A
    #pragma unroll 4
    for (int i = 0; i < 32; i++) {
        int e = i * 32 + l;
        int r = e >> 6, c2 = (e & 63) * 2;
        int m = m0 + r;
        int q = m >> 5, nn = m & 31;
        float rx = rel_s[q * 96 + nn * 3], ry = rel_s[q * 96 + nn * 3 + 1], rz = rel_s[q * 96 + nn * 3 + 2];
        float2 hp = *(const float2*)(g_h1pre + (size_t)sel_s[m] * 128 + c2);
        float2 b1 = *(const float2*)(nxb1 + c2);
        float2 w0 = *(const float2*)(nxw1 + c2);
        float2 w1 = *(const float2*)(nxw1 + 128 + c2);
        float2 w2 = *(const float2*)(nxw1 + 256 + c2);
        float v0 = fmaxf(hp.x + b1.x + rx * w0.x + ry * w1.x + rz * w2.x, 0.f);
        float v1 = fmaxf(hp.y + b1.y + rx * w0.y + ry * w1.y + rz * w2.y, 0.f);
        split_store(v0, v1, XH + (m * XP + c2) * 2, XL + (m * XP + c2) * 2);
    }
    __syncwarp();

    // Stage B
    {
        float acc[16][4];
        #pragma unroll
        for (int nt = 0; nt < 16; nt++)
            #pragma unroll
            for (int j = 0; j < 4; j++) acc[nt][j] = 0.f;
        run_mma<8, 8>(XH, XL, g_W2h, g_W2l, acc, m0, gid, tig, l);
        #pragma unroll
        for (int nt = 0; nt < 16; nt++) {
            int cb = nt * 8 + 2 * tig;
            float2 bb = *(const float2*)(nxb2 + cb);
            int r0 = m0 + gid, r1 = r0 + 8;
            split_store(fmaxf(acc[nt][0] + bb.x, 0.f), fmaxf(acc[nt][1] + bb.y, 0.f),
                        XH + (r0 * XP + cb) * 2, XL + (r0 * XP + cb) * 2);
            split_store(fmaxf(acc[nt][2] + bb.x, 0.f), fmaxf(acc[nt][3] + bb.y, 0.f),
                        XH + (r1 * XP + cb) * 2, XL + (r1 * XP + cb) * 2);
        }
    }
    __syncwarp();

    // Stage C
    {
        float acc[8][4];
        #pragma unroll
        for (int nt = 0; nt < 8; nt++)
            #pragma unroll
            for (int j = 0; j < 4; j++) acc[nt][j] = 0.f;
        run_mma<8, 4>(XH, XL, g_W3h, g_W3l, acc, m0, gid, tig, l);
        #pragma unroll
        for (int nt = 0; nt < 8; nt++) {
            int cb = nt * 8 + 2 * tig;
            float2 bb = *(const float2*)(nxb3 + cb);
            int r0 = m0 + gid, r1 = r0 + 8;
            *(float2*)(LAT + r0 * LP + cb) = make_float2(acc[nt][0] + bb.x, acc[nt][1] + bb.y);
            *(float2*)(LAT + r1 * LP + cb) = make_float2(acc[nt][2] + bb.x, acc[nt][3] + bb.y);
        }
    }
    __syncwarp();

    // Stage D
    #pragma unroll 4
    for (int i = 0; i < 16; i++) {
        int e = i * 32 + l;
        int r = e >> 5, c2 = (e & 31) * 2;
        int m = m0 + r;
        int q = m >> 5, nn = m & 31;
        float rx = rel_s[q * 96 + nn * 3], ry = rel_s[q * 96 + nn * 3 + 1], rz = rel_s[q * 96 + nn * 3 + 2];
        float2 sp = *(const float2*)(g_s1pre + (size_t)sel_s[m] * 64 + c2);
        float2 c1 = *(const float2*)(g_C1 + c2);
        float2 w0 = *(const float2*)(g_Wr1s + c2);
        float2 w1 = *(const float2*)(g_Wr1s + 64 + c2);
        float2 w2 = *(const float2*)(g_Wr1s + 128 + c2);
        float v0 = fmaxf(sp.x + c1.x + rx * w0.x + ry * w1.x + rz * w2.x, 0.f);
        float v1 = fmaxf(sp.y + c1.y + rx * w0.y + ry * w1.y + rz * w2.y, 0.f);
        split_store(v0, v1, XH + (m * XP + c2) * 2, XL + (m * XP + c2) * 2);
    }
    __syncwarp();

    // Stage E
    {
        float acc[8][4];
        #pragma unroll
        for (int nt = 0; nt < 8; nt++)
            #pragma unroll
            for (int j = 0; j < 4; j++) acc[nt][j] = 0.f;
        run_mma<4, 4>(XH, XL, g_S2h, g_S2l, acc, m0, gid, tig, l);
        #pragma unroll
        for (int nt = 0; nt < 8; nt++) {
            int cb = nt * 8 + 2 * tig;
            float2 bb = *(const float2*)(sxb2 + cb);
            int r0 = m0 + gid, r1 = r0 + 8;
            split_store(fmaxf(acc[nt][0] + bb.x, 0.f), fmaxf(acc[nt][1] + bb.y, 0.f),
                        XH + (r0 * XP + cb) * 2, XL + (r0 * XP + cb) * 2);
            split_store(fmaxf(acc[nt][2] + bb.x, 0.f), fmaxf(acc[nt][3] + bb.y, 0.f),
                        XH + (r1 * XP + cb) * 2, XL + (r1 * XP + cb) * 2);
        }
    }
    __syncwarp();

    // Stage F
    {
        float acc[8][4];
        #pragma unroll
        for (int nt = 0; nt < 8; nt++)
            #pragma unroll
            for (int j = 0; j < 4; j++) acc[nt][j] = 0.f;
        run_mma<4, 4>(XH, XL, g_S3h, g_S3l, acc, m0, gid, tig, l);
        #pragma unroll
        for (int nt = 0; nt < 8; nt++) {
            float v0 = acc[nt][0] + acc[nt][2];
            float v1 = acc[nt][1] + acc[nt][3];
            #pragma unroll
            for (int off = 16; off >= 4; off >>= 1) {
                v0 += __shfl_down_sync(0xffffffffu, v0, off);
                v1 += __shfl_down_sync(0xffffffffu, v1, off);
            }
            if (gid == 0) {
                int cb = nt * 8 + 2 * tig;
                setp[w][cb] = v0;
                setp[w][cb + 1] = v1;
            }
        }
    }
    __syncthreads();

    if (t < 16) {
        int q = t >> 2, h = t & 3;
        float s = g_Ce[h];
        #pragma unroll 8
        for (int c = 0; c < 64; c++) {
            float sf = setp[2 * q][c] + setp[2 * q + 1][c] + 32.f * sxb3[c];
            s += sf * g_A[(64 + c) * 4 + h];
        }
        gh[t] = s;
    }
    __syncthreads();
    #pragma unroll
    for (int r = 0; r < 2; r++) {
        int idx = t + r * 256;
        int q = idx >> 7, i2 = idx & 127, n = i2 >> 2, h = i2 & 3;
        int gn = q * 32 + n;
        ebuf[idx] = gh[q * 4 + h] + g_epre[(size_t)sel_s[gn] * 4 + h]
                  + rel_s[q * 96 + n * 3]     * g_A1s[h]
                  + rel_s[q * 96 + n * 3 + 1] * g_A1s[4 + h]
                  + rel_s[q * 96 + n * 3 + 2] * g_A1s[8 + h];
    }
    __syncthreads();
    if (t < 16) {
        int q = t >> 2, h = t & 3;
        float mx = -INFINITY;
        #pragma unroll
        for (int n = 0; n < 32; n++) mx = fmaxf(mx, ebuf[q * 128 + n * 4 + h]);
        float s = 0.f;
        #pragma unroll
        for (int n = 0; n < 32; n++) {
            float ex = expf(ebuf[q * 128 + n * 4 + h] - mx);
            wbuf[q * 128 + n * 4 + h] = ex;
            s += ex;
        }
        float inv = 1.f / s;
        #pragma unroll
        for (int n = 0; n < 32; n++) wbuf[q * 128 + n * 4 + h] *= inv;
    }
    __syncthreads();
    #pragma unroll
    for (int r = 0; r < 4; r++) {
        int idx = t + r * 256;
        int q = idx >> 8, i2 = idx & 255, o = i2 >> 2, h = i2 & 3;
        float s = 0.f;
        #pragma unroll
        for (int n = 0; n < 32; n++)
            s += LAT[(q * 32 + n) * LP + o] * wbuf[q * 128 + n * 4 + h];
        out[(size_t)(bk0 + q) * 256 + i2] = s;
    }
}

// ---------------------------------------------------------------------------
extern "C" void kernel_launch(void* const* d_in, const int* in_sizes, int n_in,
                              void* d_out, int out_size) {
    (void)in_sizes; (void)n_in; (void)out_size;
    const float* keys  = (const float*)d_in[0];
    const float* points= (const float*)d_in[1];
    const float* feats = (const float*)d_in[2];
    const float* nxw1  = (const float*)d_in[3];
    const float* nxb1  = (const float*)d_in[4];
    const float* nxw2  = (const float*)d_in[5];
    const float* nxb2  = (const float*)d_in[6];
    const float* nxw3  = (const float*)d_in[7];
    const float* nxb3  = (const float*)d_in[8];
    const float* sxw1  = (const float*)d_in[9];
    const float* sxb1  = (const float*)d_in[10];
    const float* sxw2  = (const float*)d_in[11];
    const float* sxb2  = (const float*)d_in[12];
    const float* sxw3  = (const float*)d_in[13];
    const float* sxb3  = (const float*)d_in[14];
    const float* attw  = (const float*)d_in[15];
    const float* attb  = (const float*)d_in[16];
    const float* attq  = (const float*)d_in[17];
    const float* gamma = (const float*)d_in[18];
    const float* beta  = (const float*)d_in[19];
    float* out = (float*)d_out;

    cudaFuncSetAttribute(k_main, cudaFuncAttributeMaxDynamicSharedMemorySize, SM_TOTAL);

    k_prep<<<2, 256>>>(attw, attb, attq);
    k_packw<<<128, 256>>>(nxw2, nxw3, sxw2, sxw3);
    k_pre_h1<<<NPTS / 8, 128>>>(feats, nxw1);
    k_knn<<<NBK, 256, 32768>>>(keys, points, feats);
    k_stats<<<64, 256>>>(gamma, beta);
    k_const<<<1, 256>>>(sxw1, sxb1);
    k_pre_s1e<<<NPTS, 64>>>(feats, sxw1);
    k_main<<<NBK / 4, 256, SM_TOTAL>>>(nxw1, nxb1, nxb2, nxb3, sxb2, sxb3, out);
}

// round 16
// speedup vs baseline: 1.1498x; 1.0270x over previous
#include <cuda_runtime.h>
#include <cuda_bf16.h>
#include <math.h>
#include <stdint.h>

#define BB 4
#define KK 2048
#define NN 4096
#define CIN 61
#define NBK (BB*KK)
#define NPTS (BB*NN)
#define KNBR 32
#define CNTF 262144.0

typedef unsigned long long ull;

// ---------------- scratch globals ----------------
__device__ float g_part[(size_t)128 * NBK];
__device__ double g_sp2[512], g_ss2[512];       // two-stage stats partials
__device__ float g_A[516];
__device__ int   g_selg[(size_t)NBK * KNBR];
__device__ float g_rel[(size_t)NBK * KNBR * 3];
__device__ float g_h1pre[(size_t)NPTS * 128];
__device__ float g_s1pre[(size_t)NPTS * 64];
__device__ float g_epre[(size_t)NPTS * 4];
__device__ float g_sc[64], g_tc[64];
__device__ float g_C1[64], g_Ce[4];
__device__ float g_Wr1s[192], g_A1s[12];
// fragment-packed bf16 weights (hi/lo)
__device__ __align__(16) __nv_bfloat16 g_W2h[16384], g_W2l[16384];
__device__ __align__(16) __nv_bfloat16 g_W3h[8192],  g_W3l[8192];
__device__ __align__(16) __nv_bfloat16 g_S2h[4096],  g_S2l[4096];
__device__ __align__(16) __nv_bfloat16 g_S3h[4096],  g_S3l[4096];

// ---------------- helpers ----------------
__device__ __forceinline__ void mma16816(float* d, const uint32_t* a, uint32_t b0, uint32_t b1) {
    asm volatile("mma.sync.aligned.m16n8k16.row.col.f32.bf16.bf16.f32 "
        "{%0,%1,%2,%3}, {%4,%5,%6,%7}, {%8,%9}, {%0,%1,%2,%3};"
        : "+f"(d[0]), "+f"(d[1]), "+f"(d[2]), "+f"(d[3])
        : "r"(a[0]), "r"(a[1]), "r"(a[2]), "r"(a[3]), "r"(b0), "r"(b1));
}
__device__ __forceinline__ void split_store(float v0, float v1, char* pH, char* pL) {
    uint32_t h;
    asm("cvt.rn.bf16x2.f32 %0, %1, %2;" : "=r"(h) : "f"(v1), "f"(v0));
    float r0 = v0 - __uint_as_float(h << 16);
    float r1 = v1 - __uint_as_float(h & 0xFFFF0000u);
    uint32_t lo;
    asm("cvt.rn.bf16x2.f32 %0, %1, %2;" : "=r"(lo) : "f"(r1), "f"(r0));
    *(uint32_t*)pH = h;
    *(uint32_t*)pL = lo;
}
__device__ __forceinline__ int wfrag_off(int n, int k, int NG) {
    int kt = k >> 4, ng = n >> 4, ntp = (n >> 3) & 1, gid = n & 7;
    int tig = (k >> 1) & 3, khalf = (k & 15) >> 3, par = k & 1;
    return kt * (NG * 512) + ng * 512 + (gid * 4 + tig) * 16 + ntp * 8 + khalf * 4 + par * 2;
}

#define XP 136
#define LP 68
#define O_XH   0
#define O_XL   34816
#define O_LAT  69632
#define SM_TOTAL 104448

extern __shared__ char smraw[];

template<int KT, int NG>
__device__ __forceinline__ void run_mma(const char* XHp, const char* XLp,
                                        const __nv_bfloat16* __restrict__ WH,
                                        const __nv_bfloat16* __restrict__ WL,
                                        float (&acc)[2*NG][4], int m0, int gid, int tig, int l) {
    #pragma unroll
    for (int kt = 0; kt < KT; kt++) {
        int k0 = kt * 16 + 2 * tig;
        const char* xa0 = XHp + ((m0 + gid) * XP + k0) * 2;
        const char* xa1 = XHp + ((m0 + gid + 8) * XP + k0) * 2;
        const char* xb0 = XLp + ((m0 + gid) * XP + k0) * 2;
        const char* xb1 = XLp + ((m0 + gid + 8) * XP + k0) * 2;
        uint32_t ah[4], al[4];
        ah[0] = *(const uint32_t*)xa0;        ah[1] = *(const uint32_t*)xa1;
        ah[2] = *(const uint32_t*)(xa0 + 16); ah[3] = *(const uint32_t*)(xa1 + 16);
        al[0] = *(const uint32_t*)xb0;        al[1] = *(const uint32_t*)xb1;
        al[2] = *(const uint32_t*)(xb0 + 16); al[3] = *(const uint32_t*)(xb1 + 16);
        #pragma unroll
        for (int ng = 0; ng < NG; ng++) {
            uint4 bh = __ldg((const uint4*)((const char*)WH + kt * (NG * 512) + ng * 512 + l * 16));
            uint4 bl = __ldg((const uint4*)((const char*)WL + kt * (NG * 512) + ng * 512 + l * 16));
            mma16816(acc[2 * ng],     ah, bh.x, bh.y);
            mma16816(acc[2 * ng],     ah, bl.x, bl.y);
            mma16816(acc[2 * ng],     al, bh.x, bh.y);
            mma16816(acc[2 * ng + 1], ah, bh.z, bh.w);
            mma16816(acc[2 * ng + 1], ah, bl.z, bl.w);
            mma16816(acc[2 * ng + 1], al, bh.z, bh.w);
        }
    }
}

// ---------------------------------------------------------------------------
__global__ void k_prep(const float* __restrict__ att_w, const float* __restrict__ att_b,
                       const float* __restrict__ att_q) {
    int t = blockIdx.x * blockDim.x + threadIdx.x;
    if (t < 512) {
        int c = t >> 2, h = t & 3;
        float s = 0.f;
        #pragma unroll 8
        for (int o = 0; o < 64; o++) s += att_w[c * 256 + h * 64 + o] * att_q[h * 64 + o];
        g_A[t] = s;
    }
    if (t < 4) {
        float s = 0.f;
        #pragma unroll 8
        for (int o = 0; o < 64; o++) s += att_b[t * 64 + o] * att_q[t * 64 + o];
        g_A[512 + t] = s;
    }
}

__global__ void __launch_bounds__(256) k_packw(const float* __restrict__ nxw2,
                                               const float* __restrict__ nxw3,
                                               const float* __restrict__ sxw2,
                                               const float* __restrict__ sxw3) {
    int t = blockIdx.x * blockDim.x + threadIdx.x;
    float v; int off; __nv_bfloat16 *dh, *dl;
    if (t < 16384) {
        int n = t >> 7, k = t & 127;
        v = nxw2[k * 128 + n]; off = wfrag_off(n, k, 8);
        dh = g_W2h; dl = g_W2l;
    } else if (t < 24576) {
        int i = t - 16384, n = i & 63, k = i >> 6;
        v = nxw3[k * 64 + n]; off = wfrag_off(n, k, 4);
        dh = g_W3h; dl = g_W3l;
    } else if (t < 28672) {
        int i = t - 24576, n = i & 63, k = i >> 6;
        v = sxw2[k * 64 + n]; off = wfrag_off(n, k, 4);
        dh = g_S2h; dl = g_S2l;
    } else {
        int i = t - 28672, n = i & 63, k = i >> 6;
        v = sxw3[k * 64 + n]; off = wfrag_off(n, k, 4);
        dh = g_S3h; dl = g_S3l;
    }
    __nv_bfloat16 hv = __float2bfloat16(v);
    __nv_bfloat16 lv = __float2bfloat16(v - __bfloat162float(hv));
    dh[off >> 1] = hv; dl[off >> 1] = lv;
}

// 8 rows per block, nxw1 feats-part staged in smem
__global__ void __launch_bounds__(128) k_pre_h1(const float* __restrict__ feats,
                                                const float* __restrict__ nxw1) {
    __shared__ float sw[61 * 128];
    __shared__ float f[8][61];
    int t = threadIdx.x;
    int row0 = blockIdx.x * 8;
    for (int i = t; i < 61 * 128; i += 128) sw[i] = nxw1[384 + i];
    for (int i = t; i < 8 * 61; i += 128) {
        int r = i / 61, c = i % 61;
        f[r][c] = feats[(size_t)(row0 + r) * 61 + c];
    }
    __syncthreads();
    #pragma unroll
    for (int r = 0; r < 8; r++) {
        float acc = 0.f;
        #pragma unroll
        for (int c = 0; c < 61; c++) acc += f[r][c] * sw[c * 128 + t];
        g_h1pre[(size_t)(row0 + r) * 128 + t] = acc;
    }
}

// block exclusive scan (256 threads)
__device__ __forceinline__ uint blk_scan_excl(uint val, volatile uint* ws, uint* tot) {
    __syncthreads();
    int lane = threadIdx.x & 31, w = threadIdx.x >> 5;
    uint inc = val;
    #pragma unroll
    for (int o = 1; o < 32; o <<= 1) {
        uint x = __shfl_up_sync(0xffffffffu, inc, o);
        if (lane >= o) inc += x;
    }
    if (lane == 31) ws[w] = inc;
    __syncthreads();
    if (threadIdx.x == 0) {
        uint run = 0;
        for (int i = 0; i < 8; i++) { uint x = ws[i]; ws[i] = run; run += x; }
        ws[8] = run;
    }
    __syncthreads();
    if (tot) *tot = ws[8];
    return inc - val + ws[w];
}

// ---------------------------------------------------------------------------
// kNN: 256 threads, radix-select with FUSED sweep 2 (hist + compaction +
// candidate extraction in one pass). dyn smem 32KB:
//   d2u[4096] | hist[2048] | candP1 ushort[3072] | cand2 ushort[1024]
// ---------------------------------------------------------------------------
__global__ void __launch_bounds__(256) k_knn(const float* __restrict__ keys,
                                             const float* __restrict__ points,
                                             const float* __restrict__ feats) {
    uint* smu  = (uint*)smraw;
    uint* d2u  = smu;
    uint* hist = smu + 4096;
    unsigned short* candP1 = (unsigned short*)(smu + 6144);
    unsigned short* cand2  = candP1 + 3072;

    __shared__ int  sel[KNBR];
    __shared__ uint ws[9];
    __shared__ int  sP1, sP2, sM2;
    __shared__ ull  wmin[8];

    int bk = blockIdx.x, b = bk >> 11, k = bk & 2047, tid = threadIdx.x;

    float kx = keys[(b * KK + k) * 3 + 0];
    float ky = keys[(b * KK + k) * 3 + 1];
    float kz = keys[(b * KK + k) * 3 + 2];
    const float* pb = points + (size_t)b * NN * 3;

    #pragma unroll
    for (int j = 0; j < 8; j++) hist[tid + j * 256] = 0;
    __syncthreads();

    // sweep 1: distances + 11-bit histogram
    #pragma unroll
    for (int j = 0; j < 16; j++) {
        int p = tid + j * 256;
        float dx = pb[p * 3 + 0] - kx;
        float dy = pb[p * 3 + 1] - ky;
        float dz = pb[p * 3 + 2] - kz;
        uint u = __float_as_uint(dx * dx + dy * dy + dz * dz);
        d2u[p] = u;
        atomicAdd(&hist[u >> 21], 1u);
    }
    __syncthreads();

    // pass 1: find pivot bin P1
    {
        uint cnt8[8], s = 0;
        #pragma unroll
        for (int j = 0; j < 8; j++) { cnt8[j] = hist[tid * 8 + j]; s += cnt8[j]; }
        uint e = blk_scan_excl(s, ws, 0);
        if (e < KNBR && e + s >= KNBR) {
            uint cum = e;
            #pragma unroll
            for (int j = 0; j < 8; j++) {
                if (cum + cnt8[j] >= KNBR) { sP1 = tid * 8 + j; break; }
                cum += cnt8[j];
            }
        }
    }
    __syncthreads();
    int P1 = sP1;

    // sweep 2 (fused): below-P1 compaction + P1 extraction + 8-bit hist
    hist[tid] = 0;
    __syncthreads();
    int m1;
    uint totP;
    {
        uint fb = 0, fp = 0;
        #pragma unroll
        for (int j = 0; j < 16; j++) {
            int p = tid + j * 256;
            uint u = d2u[p];
            int b1 = (int)(u >> 21);
            if (b1 < P1) fb |= (1u << j);
            else if (b1 == P1) {
                fp |= (1u << j);
                atomicAdd(&hist[(u >> 13) & 255], 1u);
            }
        }
        uint packed = ((uint)__popc(fb) << 16) | (uint)__popc(fp);
        uint tot;
        uint e = blk_scan_excl(packed, ws, &tot);
        int bB = (int)(e >> 16), bP = (int)(e & 0xFFFF);
        #pragma unroll
        for (int j = 0; j < 16; j++) {
            int p = tid + j * 256;
            if (fb & (1u << j)) sel[bB++] = p;
            if ((fp & (1u << j)) && bP < 3072) candP1[bP++] = (unsigned short)p;
        }
        m1 = (int)(tot >> 16);
        totP = tot & 0xFFFF;
        if (totP > 3072) totP = 3072;
    }
    __syncthreads();

    // find P2 within bin P1
    {
        uint v = hist[tid];
        uint e = blk_scan_excl(v, ws, 0);
        int need1 = KNBR - m1;
        if ((int)e < need1 && (int)(e + v) >= need1) { sP2 = tid; sM2 = (int)e; }
    }
    __syncthreads();
    int P2 = sP2, m2 = sM2;

    // classify small candP1 list: bin2<P2 -> sel, ==P2 -> cand2
    int cc;
    {
        uint fb2 = 0, fe2 = 0;
        int nIt = ((int)totP + 255) >> 8;
        for (int j = 0; j < nIt; j++) {
            int i = tid + j * 256;
            if (i < (int)totP) {
                int p = candP1[i];
                int b2 = (int)((d2u[p] >> 13) & 255);
                if (b2 < P2) fb2 |= (1u << j);
                else if (b2 == P2) fe2 |= (1u << j);
            }
        }
        uint packed = ((uint)__popc(fb2) << 16) | (uint)__popc(fe2);
        uint tot2;
        uint e = blk_scan_excl(packed, ws, &tot2);
        int bB = m1 + (int)(e >> 16), bE = (int)(e & 0xFFFF);
        for (int j = 0; j < nIt; j++) {
            int i = tid + j * 256;
            if (i < (int)totP) {
                int p = candP1[i];
                if (fb2 & (1u << j)) sel[bB++] = p;
                if ((fe2 & (1u << j)) && bE < 1024) cand2[bE++] = (unsigned short)p;
            }
        }
        cc = (int)(tot2 & 0xFFFF);
        if (cc > 1024) cc = 1024;
    }
    __syncthreads();

    // argmin rounds on boundary candidates
    {
        int m = m1 + m2, need = KNBR - m;
        for (int r = 0; r < need; r++) {
            ull best = ~0ull;
            for (int i = tid; i < cc; i += 256) {
                int p = cand2[i];
                ull key = ((ull)d2u[p] << 32) | (uint)p;
                if (key < best) best = key;
            }
            #pragma unroll
            for (int off = 16; off; off >>= 1) {
                ull o = __shfl_down_sync(0xffffffffu, best, off);
                if (o < best) best = o;
            }
            if ((tid & 31) == 0) wmin[tid >> 5] = best;
            __syncthreads();
            if (tid == 0) {
                ull bb = wmin[0];
                #pragma unroll
                for (int w = 1; w < 8; w++) if (wmin[w] < bb) bb = wmin[w];
                int p = (int)(bb & 0xFFFFFFFFull);
                sel[m + r] = p;
                d2u[p] = 0xFFFFFFFFu;
            }
            __syncthreads();
        }
    }

    // gather comb (reuse d2u region as float cs[2048])
    float* cs = (float*)smu;
    const float* fb2g = feats + (size_t)b * NN * CIN;
    __syncthreads();
    #pragma unroll
    for (int j = 0; j < 8; j++) {
        int e = tid + j * 256;
        int n = e >> 6, c = e & 63;
        int p = sel[n];
        float v;
        if (c < 3) {
            float kc = (c == 0) ? kx : ((c == 1) ? ky : kz);
            v = pb[p * 3 + c] - kc;
        } else v = fb2g[p * CIN + (c - 3)];
        cs[e] = v;
    }
    __syncthreads();

    if (tid < 64) {
        float s = 0.f, ss = 0.f;
        #pragma unroll
        for (int n = 0; n < KNBR; n++) { float v = cs[n * 64 + tid]; s += v; ss += v * v; }
        g_part[(size_t)tid * NBK + bk]        = s;
        g_part[(size_t)(64 + tid) * NBK + bk] = ss;
    }
    if (tid < 32) g_selg[(size_t)bk * 32 + tid] = b * NN + sel[tid];
    if (tid < 96) g_rel[(size_t)bk * 96 + tid] = cs[(tid / 3) * 64 + (tid % 3)];
}

// ---------------------------------------------------------------------------
// Stats stage 1: 512 blocks (64 channels x 8 slices), double partials
// ---------------------------------------------------------------------------
__global__ void __launch_bounds__(256) k_statp() {
    int c = blockIdx.x >> 3, sl = blockIdx.x & 7;
    int t = threadIdx.x;
    const float4* ps  = (const float4*)(g_part + (size_t)c * NBK + sl * 1024);
    const float4* pss = (const float4*)(g_part + (size_t)(64 + c) * NBK + sl * 1024);
    float4 a = ps[t], bq = pss[t];
    double s  = (double)a.x + (double)a.y + (double)a.z + (double)a.w;
    double ss = (double)bq.x + (double)bq.y + (double)bq.z + (double)bq.w;
    __shared__ double rs[256], rss[256];
    rs[t] = s; rss[t] = ss;
    __syncthreads();
    for (int o = 128; o; o >>= 1) {
        if (t < o) { rs[t] += rs[t + o]; rss[t] += rss[t + o]; }
        __syncthreads();
    }
    if (t == 0) { g_sp2[blockIdx.x] = rs[0]; g_ss2[blockIdx.x] = rss[0]; }
}

// ---------------------------------------------------------------------------
// k_const: finalize stats (reduce 8 slices/channel) then fold constants
// ---------------------------------------------------------------------------
__global__ void k_const(const float* __restrict__ gamma, const float* __restrict__ beta,
                        const float* __restrict__ sxw1, const float* __restrict__ sxb1) {
    __shared__ float ssc[64], stc[64];
    int t = threadIdx.x;
    if (t < 64) {
        double s = 0.0, ss = 0.0;
        #pragma unroll
        for (int sl = 0; sl < 8; sl++) { s += g_sp2[t * 8 + sl]; ss += g_ss2[t * 8 + sl]; }
        double mean = s / CNTF;
        double var  = ss / CNTF - mean * mean;
        float sc = (float)((1.0 / sqrt(var + 1e-5)) * (double)gamma[t]);
        float tc = beta[t] - (float)mean * sc;
        g_sc[t] = sc; g_tc[t] = tc;
        ssc[t] = sc; stc[t] = tc;
    }
    __syncthreads();
    if (t < 64) {
        float s = sxb1[t];
        #pragma unroll 8
        for (int c = 0; c < 64; c++) s += stc[c] * sxw1[c * 64 + t];
        g_C1[t] = s;
    }
    if (t < 4) {
        float s = g_A[512 + t];
        #pragma unroll 8
        for (int c = 0; c < 64; c++) s += stc[c] * g_A[c * 4 + t];
        g_Ce[t] = s;
    }
    if (t >= 64) {
        int i = t - 64, c = i >> 6, o = i & 63;
        g_Wr1s[i] = ssc[c] * sxw1[c * 64 + o];
    }
    if (t < 12) g_A1s[t] = ssc[t >> 2] * g_A[(t >> 2) * 4 + (t & 3)];
}

// 8 rows per block, sxw1 + att rows staged in smem (R12-verified)
__global__ void __launch_bounds__(128) k_pre_s1e(const float* __restrict__ feats,
                                                 const float* __restrict__ sxw1) {
    __shared__ float sw[61 * 64];
    __shared__ float sa[244];
    __shared__ float sf[8][61];
    int t = threadIdx.x;
    int row0 = blockIdx.x * 8;
    for (int i = t; i < 61 * 64; i += 128) {
        int c = i >> 6, o = i & 63;
        sw[i] = sxw1[(3 + c) * 64 + o];
    }
    for (int i = t; i < 244; i += 128) sa[i] = g_A[12 + i];
    for (int i = t; i < 8 * 61; i += 128) {
        int r = i / 61, c = i % 61;
        sf[r][c] = feats[(size_t)(row0 + r) * 61 + c] * g_sc[3 + c];
    }
    __syncthreads();
    int o = t & 63, rb = (t >> 6) * 4;
    #pragma unroll
    for (int r = 0; r < 4; r++) {
        float acc = 0.f;
        #pragma unroll
        for (int c = 0; c < 61; c++) acc += sf[rb + r][c] * sw[(c << 6) + o];
        g_s1pre[(size_t)(row0 + rb + r) * 64 + o] = acc;
    }
    if (t < 32) {
        int r = t >> 2, h = t & 3;
        float s = 0.f;
        #pragma unroll
        for (int c = 0; c < 61; c++) s += sf[r][c] * sa[c * 4 + h];
        g_epre[(size_t)(row0 + r) * 4 + h] = s;
    }
}

// ---------------------------------------------------------------------------
// k_main: unchanged verified config (230.9µs measured; 82% of HMMA floor).
// ---------------------------------------------------------------------------
__global__ void __launch_bounds__(256, 2) k_main(
    const float* __restrict__ nxw1, const float* __restrict__ nxb1,
    const float* __restrict__ nxb2, const float* __restrict__ nxb3,
    const float* __restrict__ sxb2, const float* __restrict__ sxb3,
    float* __restrict__ out)
{
    char* XH  = smraw + O_XH;
    char* XL  = smraw + O_XL;
    float* LAT = (float*)(smraw + O_LAT);

    __shared__ int   sel_s[128];
    __shared__ float rel_s[384];
    __shared__ float setp[8][64];
    __shared__ float gh[16];
    __shared__ float ebuf[512];
    __shared__ float wbuf[512];

    int t = threadIdx.x, w = t >> 5, l = t & 31;
    int gid = l >> 2, tig = l & 3;
    int m0 = w * 16;
    int bk0 = blockIdx.x * 4;

    if (t < 128) sel_s[t] = g_selg[(size_t)bk0 * 32 + t];
    for (int i = t; i < 384; i += 256) rel_s[i] = g_rel[(size_t)bk0 * 96 + i];
    __syncthreads();

    // Stage A
    #pragma unroll 4
    for (int i = 0; i < 32; i++) {
        int e = i * 32 + l;
        int r = e >> 6, c2 = (e & 63) * 2;
        int m = m0 + r;
        int q = m >> 5, nn = m & 31;
        float rx = rel_s[q * 96 + nn * 3], ry = rel_s[q * 96 + nn * 3 + 1], rz = rel_s[q * 96 + nn * 3 + 2];
        float2 hp = *(const float2*)(g_h1pre + (size_t)sel_s[m] * 128 + c2);
        float2 b1 = *(const float2*)(nxb1 + c2);
        float2 w0 = *(const float2*)(nxw1 + c2);
        float2 w1 = *(const float2*)(nxw1 + 128 + c2);
        float2 w2 = *(const float2*)(nxw1 + 256 + c2);
        float v0 = fmaxf(hp.x + b1.x + rx * w0.x + ry * w1.x + rz * w2.x, 0.f);
        float v1 = fmaxf(hp.y + b1.y + rx * w0.y + ry * w1.y + rz * w2.y, 0.f);
        split_store(v0, v1, XH + (m * XP + c2) * 2, XL + (m * XP + c2) * 2);
    }
    __syncwarp();

    // Stage B
    {
        float acc[16][4];
        #pragma unroll
        for (int nt = 0; nt < 16; nt++)
            #pragma unroll
            for (int j = 0; j < 4; j++) acc[nt][j] = 0.f;
        run_mma<8, 8>(XH, XL, g_W2h, g_W2l, acc, m0, gid, tig, l);
        #pragma unroll
        for (int nt = 0; nt < 16; nt++) {
            int cb = nt * 8 + 2 * tig;
            float2 bb = *(const float2*)(nxb2 + cb);
            int r0 = m0 + gid, r1 = r0 + 8;
            split_store(fmaxf(acc[nt][0] + bb.x, 0.f), fmaxf(acc[nt][1] + bb.y, 0.f),
                        XH + (r0 * XP + cb) * 2, XL + (r0 * XP + cb) * 2);
            split_store(fmaxf(acc[nt][2] + bb.x, 0.f), fmaxf(acc[nt][3] + bb.y, 0.f),
                        XH + (r1 * XP + cb) * 2, XL + (r1 * XP + cb) * 2);
        }
    }
    __syncwarp();

    // Stage C
    {
        float acc[8][4];
        #pragma unroll
        for (int nt = 0; nt < 8; nt++)
            #pragma unroll
            for (int j = 0; j < 4; j++) acc[nt][j] = 0.f;
        run_mma<8, 4>(XH, XL, g_W3h, g_W3l, acc, m0, gid, tig, l);
        #pragma unroll
        for (int nt = 0; nt < 8; nt++) {
            int cb = nt * 8 + 2 * tig;
            float2 bb = *(const float2*)(nxb3 + cb);
            int r0 = m0 + gid, r1 = r0 + 8;
            *(float2*)(LAT + r0 * LP + cb) = make_float2(acc[nt][0] + bb.x, acc[nt][1] + bb.y);
            *(float2*)(LAT + r1 * LP + cb) = make_float2(acc[nt][2] + bb.x, acc[nt][3] + bb.y);
        }
    }
    __syncwarp();

    // Stage D
    #pragma unroll 4
    for (int i = 0; i < 16; i++) {
        int e = i * 32 + l;
        int r = e >> 5, c2 = (e & 31) * 2;
        int m = m0 + r;
        int q = m >> 5, nn = m & 31;
        float rx = rel_s[q * 96 + nn * 3], ry = rel_s[q * 96 + nn * 3 + 1], rz = rel_s[q * 96 + nn * 3 + 2];
        float2 sp = *(const float2*)(g_s1pre + (size_t)sel_s[m] * 64 + c2);
        float2 c1 = *(const float2*)(g_C1 + c2);
        float2 w0 = *(const float2*)(g_Wr1s + c2);
        float2 w1 = *(const float2*)(g_Wr1s + 64 + c2);
        float2 w2 = *(const float2*)(g_Wr1s + 128 + c2);
        float v0 = fmaxf(sp.x + c1.x + rx * w0.x + ry * w1.x + rz * w2.x, 0.f);
        float v1 = fmaxf(sp.y + c1.y + rx * w0.y + ry * w1.y + rz * w2.y, 0.f);
        split_store(v0, v1, XH + (m * XP + c2) * 2, XL + (m * XP + c2) * 2);
    }
    __syncwarp();

    // Stage E
    {
        float acc[8][4];
        #pragma unroll
        for (int nt = 0; nt < 8; nt++)
            #pragma unroll
            for (int j = 0; j < 4; j++) acc[nt][j] = 0.f;
        run_mma<4, 4>(XH, XL, g_S2h, g_S2l, acc, m0, gid, tig, l);
        #pragma unroll
        for (int nt = 0; nt < 8; nt++) {
            int cb = nt * 8 + 2 * tig;
            float2 bb = *(const float2*)(sxb2 + cb);
            int r0 = m0 + gid, r1 = r0 + 8;
            split_store(fmaxf(acc[nt][0] + bb.x, 0.f), fmaxf(acc[nt][1] + bb.y, 0.f),
                        XH + (r0 * XP + cb) * 2, XL + (r0 * XP + cb) * 2);
            split_store(fmaxf(acc[nt][2] + bb.x, 0.f), fmaxf(acc[nt][3] + bb.y, 0.f),
                        XH + (r1 * XP + cb) * 2, XL + (r1 * XP + cb) * 2);
        }
    }
    __syncwarp();

    // Stage F
    {
        float acc[8][4];
        #pragma unroll
        for (int nt = 0; nt < 8; nt++)
            #pragma unroll
            for (int j = 0; j < 4; j++) acc[nt][j] = 0.f;
        run_mma<4, 4>(XH, XL, g_S3h, g_S3l, acc, m0, gid, tig, l);
        #pragma unroll
        for (int nt = 0; nt < 8; nt++) {
            float v0 = acc[nt][0] + acc[nt][2];
            float v1 = acc[nt][1] + acc[nt][3];
            #pragma unroll
            for (int off = 16; off >= 4; off >>= 1) {
                v0 += __shfl_down_sync(0xffffffffu, v0, off);
                v1 += __shfl_down_sync(0xffffffffu, v1, off);
            }
            if (gid == 0) {
                int cb = nt * 8 + 2 * tig;
                setp[w][cb] = v0;
                setp[w][cb + 1] = v1;
            }
        }
    }
    __syncthreads();

    if (t < 16) {
        int q = t >> 2, h = t & 3;
        float s = g_Ce[h];
        #pragma unroll 8
        for (int c = 0; c < 64; c++) {
            float sf = setp[2 * q][c] + setp[2 * q + 1][c] + 32.f * sxb3[c];
            s += sf * g_A[(64 + c) * 4 + h];
        }
        gh[t] = s;
    }
    __syncthreads();
    #pragma unroll
    for (int r = 0; r < 2; r++) {
        int idx = t + r * 256;
        int q = idx >> 7, i2 = idx & 127, n = i2 >> 2, h = i2 & 3;
        int gn = q * 32 + n;
        ebuf[idx] = gh[q * 4 + h] + g_epre[(size_t)sel_s[gn] * 4 + h]
                  + rel_s[q * 96 + n * 3]     * g_A1s[h]
                  + rel_s[q * 96 + n * 3 + 1] * g_A1s[4 + h]
                  + rel_s[q * 96 + n * 3 + 2] * g_A1s[8 + h];
    }
    __syncthreads();
    if (t < 16) {
        int q = t >> 2, h = t & 3;
        float mx = -INFINITY;
        #pragma unroll
        for (int n = 0; n < 32; n++) mx = fmaxf(mx, ebuf[q * 128 + n * 4 + h]);
        float s = 0.f;
        #pragma unroll
        for (int n = 0; n < 32; n++) {
            float ex = expf(ebuf[q * 128 + n * 4 + h] - mx);
            wbuf[q * 128 + n * 4 + h] = ex;
            s += ex;
        }
        float inv = 1.f / s;
        #pragma unroll
        for (int n = 0; n < 32; n++) wbuf[q * 128 + n * 4 + h] *= inv;
    }
    __syncthreads();
    #pragma unroll
    for (int r = 0; r < 4; r++) {
        int idx = t + r * 256;
        int q = idx >> 8, i2 = idx & 255, o = i2 >> 2, h = i2 & 3;
        float s = 0.f;
        #pragma unroll
        for (int n = 0; n < 32; n++)
            s += LAT[(q * 32 + n) * LP + o] * wbuf[q * 128 + n * 4 + h];
        out[(size_t)(bk0 + q) * 256 + i2] = s;
    }
}

// ---------------------------------------------------------------------------
extern "C" void kernel_launch(void* const* d_in, const int* in_sizes, int n_in,
                              void* d_out, int out_size) {
    (void)in_sizes; (void)n_in; (void)out_size;
    const float* keys  = (const float*)d_in[0];
    const float* points= (const float*)d_in[1];
    const float* feats = (const float*)d_in[2];
    const float* nxw1  = (const float*)d_in[3];
    const float* nxb1  = (const float*)d_in[4];
    const float* nxw2  = (const float*)d_in[5];
    const float* nxb2  = (const float*)d_in[6];
    const float* nxw3  = (const float*)d_in[7];
    const float* nxb3  = (const float*)d_in[8];
    const float* sxw1  = (const float*)d_in[9];
    const float* sxb1  = (const float*)d_in[10];
    const float* sxw2  = (const float*)d_in[11];
    const float* sxb2  = (const float*)d_in[12];
    const float* sxw3  = (const float*)d_in[13];
    const float* sxb3  = (const float*)d_in[14];
    const float* attw  = (const float*)d_in[15];
    const float* attb  = (const float*)d_in[16];
    const float* attq  = (const float*)d_in[17];
    const float* gamma = (const float*)d_in[18];
    const float* beta  = (const float*)d_in[19];
    float* out = (float*)d_out;

    cudaFuncSetAttribute(k_main, cudaFuncAttributeMaxDynamicSharedMemorySize, SM_TOTAL);

    k_prep<<<2, 256>>>(attw, attb, attq);
    k_packw<<<128, 256>>>(nxw2, nxw3, sxw2, sxw3);
    k_pre_h1<<<NPTS / 8, 128>>>(feats, nxw1);
    k_knn<<<NBK, 256, 32768>>>(keys, points, feats);
    k_statp<<<512, 256>>>();
    k_const<<<1, 256>>>(gamma, beta, sxw1, sxb1);
    k_pre_s1e<<<NPTS / 8, 128>>>(feats, sxw1);
    k_main<<<NBK / 4, 256, SM_TOTAL>>>(nxw1, nxb1, nxb2, nxb3, sxb2, sxb3, out);
}